// round 1
// baseline (speedup 1.0000x reference)
#include <cuda_runtime.h>
#include <cuda_bf16.h>
#include <math.h>

// Problem constants
#define BB     8
#define LL     1024
#define DIN    64
#define DM     256
#define NL     4
#define DS     16
#define DC     4
#define DI     512
#define DTR    16
#define BL     (BB*LL)        // 8192
#define XZW    (2*DI)         // 1024
#define XDBLW  (DTR+2*DS)     // 48

// ---------------------------------------------------------------------------
// Scratch (no cudaMalloc allowed)
// ---------------------------------------------------------------------------
__device__ __align__(16) float g_h   [BL*DM];     //  8.4 MB
__device__ __align__(16) float g_hn  [BL*DM];     //  8.4 MB
__device__ __align__(16) float g_xz  [BL*XZW];    // 33.6 MB
__device__ __align__(16) float g_xc  [BL*DI];     // 16.8 MB
__device__ __align__(16) float g_xdbl[BL*XDBLW];  //  1.6 MB
__device__ __align__(16) float g_y   [BL*DI];     // 16.8 MB

// ---------------------------------------------------------------------------
// Generic fp32 GEMM:  C[M,N] (+)= A[M,K] * B[N,K]^T  (+ bias[n])
// A row-major (K contiguous), B row-major (K contiguous).
// M must be a multiple of 64; K a multiple of 16; N arbitrary.
// ---------------------------------------------------------------------------
#define GBM 64
#define GBN 64
#define GBK 16

template<bool BIAS, bool ACCUM>
__global__ void __launch_bounds__(128)
gemm_nt(const float* __restrict__ A, const float* __restrict__ B,
        const float* __restrict__ bias, float* __restrict__ C,
        int M, int N, int K)
{
    __shared__ float As[GBK][GBM];
    __shared__ float Bs[GBK][GBN];

    const int tid = threadIdx.x;
    const int m0  = blockIdx.y * GBM;
    const int n0  = blockIdx.x * GBN;
    const int tr  = tid >> 4;    // 0..7  (8 m-rows of 8)
    const int tc  = tid & 15;    // 0..15 (16 n-cols of 4)

    float acc[8][4];
#pragma unroll
    for (int i = 0; i < 8; i++)
#pragma unroll
        for (int j = 0; j < 4; j++) acc[i][j] = 0.f;

    for (int ko = 0; ko < K; ko += GBK) {
        // load tiles: 64x16 floats = 256 float4, 128 threads -> 2 each
#pragma unroll
        for (int i = 0; i < 2; i++) {
            int f   = tid + i * 128;
            int row = f >> 2;
            int kk  = (f & 3) << 2;
            float4 a = *reinterpret_cast<const float4*>(
                &A[(size_t)(m0 + row) * K + ko + kk]);
            As[kk + 0][row] = a.x; As[kk + 1][row] = a.y;
            As[kk + 2][row] = a.z; As[kk + 3][row] = a.w;
            float4 bv = make_float4(0.f, 0.f, 0.f, 0.f);
            if (n0 + row < N)
                bv = *reinterpret_cast<const float4*>(
                    &B[(size_t)(n0 + row) * K + ko + kk]);
            Bs[kk + 0][row] = bv.x; Bs[kk + 1][row] = bv.y;
            Bs[kk + 2][row] = bv.z; Bs[kk + 3][row] = bv.w;
        }
        __syncthreads();

#pragma unroll
        for (int k = 0; k < GBK; k++) {
            float4 a0 = *reinterpret_cast<const float4*>(&As[k][tr * 8]);
            float4 a1 = *reinterpret_cast<const float4*>(&As[k][tr * 8 + 4]);
            float4 b0 = *reinterpret_cast<const float4*>(&Bs[k][tc * 4]);
            float am[8] = {a0.x, a0.y, a0.z, a0.w, a1.x, a1.y, a1.z, a1.w};
            float bn[4] = {b0.x, b0.y, b0.z, b0.w};
#pragma unroll
            for (int i = 0; i < 8; i++)
#pragma unroll
                for (int j = 0; j < 4; j++)
                    acc[i][j] = fmaf(am[i], bn[j], acc[i][j]);
        }
        __syncthreads();
    }

#pragma unroll
    for (int i = 0; i < 8; i++) {
        int gm = m0 + tr * 8 + i;
#pragma unroll
        for (int j = 0; j < 4; j++) {
            int gn = n0 + tc * 4 + j;
            if (gn < N) {
                float v = acc[i][j];
                if (BIAS)  v += bias[gn];
                if (ACCUM) v += C[(size_t)gm * N + gn];
                C[(size_t)gm * N + gn] = v;
            }
        }
    }
}

// ---------------------------------------------------------------------------
// Row LayerNorm over width 256 (one warp per row, 8 elems/thread)
// ---------------------------------------------------------------------------
__global__ void __launch_bounds__(256)
ln_rows(const float* __restrict__ in, float* __restrict__ out,
        const float* __restrict__ g, const float* __restrict__ b)
{
    int w    = (blockIdx.x * blockDim.x + threadIdx.x) >> 5; // row
    int lane = threadIdx.x & 31;
    const float* r = in + (size_t)w * DM;

    float v[8];
    float s = 0.f;
#pragma unroll
    for (int k = 0; k < 8; k++) { v[k] = r[k * 32 + lane]; s += v[k]; }
#pragma unroll
    for (int o = 16; o; o >>= 1) s += __shfl_xor_sync(0xffffffffu, s, o);
    float mu = s * (1.f / 256.f);

    float q = 0.f;
#pragma unroll
    for (int k = 0; k < 8; k++) { float d = v[k] - mu; q += d * d; }
#pragma unroll
    for (int o = 16; o; o >>= 1) q += __shfl_xor_sync(0xffffffffu, q, o);
    float rs = rsqrtf(q * (1.f / 256.f) + 1e-5f);

    float* o2 = out + (size_t)w * DM;
#pragma unroll
    for (int k = 0; k < 8; k++) {
        int e = k * 32 + lane;
        o2[e] = (v[k] - mu) * rs * g[e] + b[e];
    }
}

// ---------------------------------------------------------------------------
// Causal depthwise conv (width 4) + SiLU.  Input = xz[..., 0:DI]
// ---------------------------------------------------------------------------
__global__ void __launch_bounds__(256)
conv_silu(const float* __restrict__ xz, const float* __restrict__ cw,
          const float* __restrict__ cb, float* __restrict__ xc)
{
    int r = blockIdx.x;                       // 0..8191
    int d = blockIdx.y * 256 + threadIdx.x;   // 0..511
    int l = r & (LL - 1);

    float acc = cb[d];
#pragma unroll
    for (int k = 0; k < DC; k++) {
        int lp = l - (DC - 1) + k;
        if (lp >= 0)
            acc = fmaf(xz[(size_t)(r - (DC - 1) + k) * XZW + d], cw[d * DC + k], acc);
    }
    // SiLU
    acc = acc / (1.f + __expf(-acc));
    xc[(size_t)r * DI + d] = acc;
}

// ---------------------------------------------------------------------------
// Selective scan, fused dt-projection + softplus + gating.
// One warp per block; thread owns one (b, d) lane, 16-state in registers.
// Software-pipelined global loads (1 step lookahead).
// ---------------------------------------------------------------------------
__global__ void __launch_bounds__(32)
scan_kernel(const float* __restrict__ xc, const float* __restrict__ xdbl,
            const float* __restrict__ xz, const float* __restrict__ wdtw,
            const float* __restrict__ wdtb, const float* __restrict__ Alog,
            const float* __restrict__ Dp, float* __restrict__ y)
{
    const int b    = blockIdx.x;                 // 0..7
    const int lane = threadIdx.x;                // 0..31
    const int d    = blockIdx.y * 32 + lane;     // 0..511

    __shared__ float sd[2][XDBLW];

    float wdt[DTR], Av[DS], h[DS];
#pragma unroll
    for (int r = 0; r < DTR; r++) wdt[r] = wdtw[d * DTR + r];
#pragma unroll
    for (int s = 0; s < DS; s++) { Av[s] = -expf(Alog[d * DS + s]); h[s] = 0.f; }
    const float dtb = wdtb[d];
    const float Dv  = Dp[d];

    const size_t base = (size_t)b * LL;

    // preload step 0
    sd[0][lane] = xdbl[base * XDBLW + lane];
    if (lane < XDBLW - 32) sd[0][32 + lane] = xdbl[base * XDBLW + 32 + lane];
    float xv = xc[base * DI + d];
    float zv = xz[base * XZW + DI + d];
    __syncwarp();

    for (int l = 0; l < LL; l++) {
        const int cur = l & 1, nxt = cur ^ 1;

        // issue next-step loads early (overlap with compute)
        float xv_n = 0.f, zv_n = 0.f, p0 = 0.f, p1 = 0.f;
        if (l < LL - 1) {
            size_t nb = base + l + 1;
            xv_n = xc[nb * DI + d];
            zv_n = xz[nb * XZW + DI + d];
            p0   = xdbl[nb * XDBLW + lane];
            if (lane < XDBLW - 32) p1 = xdbl[nb * XDBLW + 32 + lane];
        }

        // dt = softplus(wdt . dt_r + dtb)
        float dtl = dtb;
#pragma unroll
        for (int r = 0; r < DTR; r++) dtl = fmaf(wdt[r], sd[cur][r], dtl);
        float dt = (dtl > 20.f) ? dtl : log1pf(__expf(dtl));

        float dtx = dt * xv;
        float yv  = xv * Dv;
#pragma unroll
        for (int s = 0; s < DS; s++) {
            float dA = __expf(dt * Av[s]);
            h[s] = fmaf(dA, h[s], dtx * sd[cur][DTR + s]);
            yv   = fmaf(h[s], sd[cur][DTR + DS + s], yv);
        }

        // gate by silu(z)
        yv *= zv / (1.f + __expf(-zv));
        y[(base + l) * DI + d] = yv;

        // stage next step
        sd[nxt][lane] = p0;
        if (lane < XDBLW - 32) sd[nxt][32 + lane] = p1;
        xv = xv_n; zv = zv_n;
        __syncwarp();
    }
}

// ---------------------------------------------------------------------------
// Final LayerNorm + mean over L.  One block per batch.
// ---------------------------------------------------------------------------
__global__ void __launch_bounds__(256)
final_ln_mean(const float* __restrict__ hm, const float* __restrict__ g,
              const float* __restrict__ b, float* __restrict__ out)
{
    const int bi   = blockIdx.x;
    const int w    = threadIdx.x >> 5;
    const int lane = threadIdx.x & 31;

    float acc[8];
#pragma unroll
    for (int k = 0; k < 8; k++) acc[k] = 0.f;

    for (int l = w; l < LL; l += 8) {
        const float* r = hm + ((size_t)bi * LL + l) * DM;
        float v[8];
        float s = 0.f;
#pragma unroll
        for (int k = 0; k < 8; k++) { v[k] = r[k * 32 + lane]; s += v[k]; }
#pragma unroll
        for (int o = 16; o; o >>= 1) s += __shfl_xor_sync(0xffffffffu, s, o);
        float mu = s * (1.f / 256.f);
        float q = 0.f;
#pragma unroll
        for (int k = 0; k < 8; k++) { float dd = v[k] - mu; q += dd * dd; }
#pragma unroll
        for (int o = 16; o; o >>= 1) q += __shfl_xor_sync(0xffffffffu, q, o);
        float rs = rsqrtf(q * (1.f / 256.f) + 1e-5f);
#pragma unroll
        for (int k = 0; k < 8; k++) {
            int e = k * 32 + lane;
            acc[k] += (v[k] - mu) * rs * g[e] + b[e];
        }
    }

    __shared__ float sm[8 * DM];
#pragma unroll
    for (int k = 0; k < 8; k++) sm[w * DM + k * 32 + lane] = acc[k];
    __syncthreads();

    int e = threadIdx.x; // 0..255
    float s = 0.f;
#pragma unroll
    for (int w2 = 0; w2 < 8; w2++) s += sm[w2 * DM + e];
    out[bi * DM + e] = s * (1.f / (float)LL);
}

// ---------------------------------------------------------------------------
// Host launch
// ---------------------------------------------------------------------------
extern "C" void kernel_launch(void* const* d_in, const int* in_sizes, int n_in,
                              void* d_out, int out_size)
{
    const float* x       = (const float*)d_in[0];
    const float* inp_w   = (const float*)d_in[1];
    const float* inp_b   = (const float*)d_in[2];
    const float* ln_g    = (const float*)d_in[3];
    const float* ln_b    = (const float*)d_in[4];
    const float* win_w   = (const float*)d_in[5];
    const float* conv_w  = (const float*)d_in[6];
    const float* conv_b  = (const float*)d_in[7];
    const float* wx_w    = (const float*)d_in[8];
    const float* wdt_w   = (const float*)d_in[9];
    const float* wdt_b   = (const float*)d_in[10];
    const float* A_log   = (const float*)d_in[11];
    const float* D_p     = (const float*)d_in[12];
    const float* wout_w  = (const float*)d_in[13];
    const float* out_g   = (const float*)d_in[14];
    const float* out_b   = (const float*)d_in[15];
    float* out = (float*)d_out;

    float *ph, *phn, *pxz, *pxc, *pxdbl, *py;
    cudaGetSymbolAddress((void**)&ph,    g_h);
    cudaGetSymbolAddress((void**)&phn,   g_hn);
    cudaGetSymbolAddress((void**)&pxz,   g_xz);
    cudaGetSymbolAddress((void**)&pxc,   g_xc);
    cudaGetSymbolAddress((void**)&pxdbl, g_xdbl);
    cudaGetSymbolAddress((void**)&py,    g_y);

    // input projection: h = x @ inp_w^T + inp_b   (8192x256, K=64)
    gemm_nt<true, false><<<dim3(DM / GBN, BL / GBM), 128>>>(
        x, inp_w, inp_b, ph, BL, DM, DIN);

    for (int l = 0; l < NL; l++) {
        const float* lw_g   = ln_g   + (size_t)l * DM;
        const float* lw_b   = ln_b   + (size_t)l * DM;
        const float* w_in   = win_w  + (size_t)l * XZW * DM;
        const float* w_cv   = conv_w + (size_t)l * DI * DC;
        const float* b_cv   = conv_b + (size_t)l * DI;
        const float* w_x    = wx_w   + (size_t)l * XDBLW * DI;
        const float* w_dt   = wdt_w  + (size_t)l * DI * DTR;
        const float* b_dt   = wdt_b  + (size_t)l * DI;
        const float* a_log  = A_log  + (size_t)l * DI * DS;
        const float* d_pl   = D_p    + (size_t)l * DI;
        const float* w_out  = wout_w + (size_t)l * DM * DI;

        // 1) layernorm
        ln_rows<<<BL / 8, 256>>>(ph, phn, lw_g, lw_b);
        // 2) xz = hn @ win^T   (8192x1024, K=256)
        gemm_nt<false, false><<<dim3(XZW / GBN, BL / GBM), 128>>>(
            phn, w_in, nullptr, pxz, BL, XZW, DM);
        // 3) conv + silu
        conv_silu<<<dim3(BL, DI / 256), 256>>>(pxz, w_cv, b_cv, pxc);
        // 4) x_dbl = xc @ wx^T   (8192x48, K=512)
        gemm_nt<false, false><<<dim3(1, BL / GBM), 128>>>(
            pxc, w_x, nullptr, pxdbl, BL, XDBLW, DI);
        // 5) selective scan (fused dt-proj + softplus + D skip + z-gate)
        scan_kernel<<<dim3(BB, DI / 32), 32>>>(
            pxc, pxdbl, pxz, w_dt, b_dt, a_log, d_pl, py);
        // 6) h += y @ wout^T   (8192x256, K=512)
        gemm_nt<false, true><<<dim3(DM / GBN, BL / GBM), 128>>>(
            py, w_out, nullptr, ph, BL, DM, DI);
    }

    // final layernorm + mean over L
    final_ln_mean<<<BB, 256>>>(ph, out_g, out_b, out);
}